// round 2
// baseline (speedup 1.0000x reference)
#include <cuda_runtime.h>

// Problem dims (fixed by the dataset)
#define BB 4
#define SS 2048
#define DD 1024
#define UU 1024

// Scratch: Q, K, V, context  (4 x 32MB = 128MB, static device globals)
__device__ float g_q[BB * SS * UU];
__device__ float g_k[BB * SS * UU];
__device__ float g_v[BB * SS * UU];
__device__ float g_ctx[BB * SS * UU];

// ---------------------------------------------------------------------------
// Tiled SGEMM: C = alpha * A * op(B) (+ bias)
//   A: M x K row-major      op(B): K x N  (TRANSB=0: B is KxN;  TRANSB=1: B is NxK)
//   64x64 block tile, BK=16, 256 threads, 4x4 per-thread microtile.
//   All dims here are multiples of 64/16 -> no bounds checks.
// ---------------------------------------------------------------------------
#define BM 64
#define BN 64
#define BK 16

template <bool TRANSB, bool HASBIAS, bool HASALPHA>
__global__ __launch_bounds__(256) void gemm_kernel(
    const float* __restrict__ A, const float* __restrict__ Bm,
    float* __restrict__ C, int M, int N, int K,
    long sA, long sB, long sC,
    const float* __restrict__ bias, const float* __restrict__ alpha_ptr)
{
    A  += (long)blockIdx.z * sA;
    Bm += (long)blockIdx.z * sB;
    C  += (long)blockIdx.z * sC;

    __shared__ float As[BK][BM + 4];   // stored transposed (k-major)
    __shared__ float Bs[BK][BN + 4];

    const int tid = threadIdx.x;
    const int tx = tid & 15;           // 0..15  -> column group
    const int ty = tid >> 4;           // 0..15  -> row group
    const int row0 = blockIdx.y * BM;
    const int col0 = blockIdx.x * BN;

    // A tile load: 64 rows x 16 cols, one float4 per thread
    const int a_row = tid >> 2;              // 0..63
    const int a_col = (tid & 3) * 4;         // 0,4,8,12

    float acc[4][4];
#pragma unroll
    for (int i = 0; i < 4; i++)
#pragma unroll
        for (int j = 0; j < 4; j++) acc[i][j] = 0.0f;

    for (int k0 = 0; k0 < K; k0 += BK) {
        // --- load A tile (transposed into SMEM) ---
        float4 av = *(const float4*)&A[(long)(row0 + a_row) * K + (k0 + a_col)];
        As[a_col + 0][a_row] = av.x;
        As[a_col + 1][a_row] = av.y;
        As[a_col + 2][a_row] = av.z;
        As[a_col + 3][a_row] = av.w;

        // --- load B tile ---
        if (!TRANSB) {
            // B is K x N: tile is BK rows x BN cols
            const int br = tid >> 4;             // 0..15
            const int bc = (tid & 15) * 4;       // 0..60
            float4 bv = *(const float4*)&Bm[(long)(k0 + br) * N + (col0 + bc)];
            Bs[br][bc + 0] = bv.x;
            Bs[br][bc + 1] = bv.y;
            Bs[br][bc + 2] = bv.z;
            Bs[br][bc + 3] = bv.w;
        } else {
            // B is N x K: tile is BN rows x BK cols, store transposed
            const int br = tid >> 2;             // 0..63
            const int bc = (tid & 3) * 4;        // 0,4,8,12
            float4 bv = *(const float4*)&Bm[(long)(col0 + br) * K + (k0 + bc)];
            Bs[bc + 0][br] = bv.x;
            Bs[bc + 1][br] = bv.y;
            Bs[bc + 2][br] = bv.z;
            Bs[bc + 3][br] = bv.w;
        }
        __syncthreads();

        // --- compute ---
#pragma unroll
        for (int k = 0; k < BK; k++) {
            float4 a0 = *(const float4*)&As[k][ty * 4];
            float4 b0 = *(const float4*)&Bs[k][tx * 4];
            float a[4] = {a0.x, a0.y, a0.z, a0.w};
            float b[4] = {b0.x, b0.y, b0.z, b0.w};
#pragma unroll
            for (int i = 0; i < 4; i++)
#pragma unroll
                for (int j = 0; j < 4; j++)
                    acc[i][j] = fmaf(a[i], b[j], acc[i][j]);
        }
        __syncthreads();
    }

    const float alpha = HASALPHA ? *alpha_ptr : 1.0f;

#pragma unroll
    for (int i = 0; i < 4; i++) {
        const int r = row0 + ty * 4 + i;
        float4 o;
        o.x = acc[i][0] * alpha;
        o.y = acc[i][1] * alpha;
        o.z = acc[i][2] * alpha;
        o.w = acc[i][3] * alpha;
        if (HASBIAS) {
            const int c = col0 + tx * 4;
            o.x += bias[c + 0];
            o.y += bias[c + 1];
            o.z += bias[c + 2];
            o.w += bias[c + 3];
        }
        *(float4*)&C[(long)r * N + (col0 + tx * 4)] = o;
    }
}

// ---------------------------------------------------------------------------
// Row softmax, in place. One block per row. ncols = 2048.
// ---------------------------------------------------------------------------
__global__ __launch_bounds__(256) void softmax_rows(float* __restrict__ data, int ncols)
{
    __shared__ float red[256];
    float* row = data + (long)blockIdx.x * ncols;
    const int tid = threadIdx.x;

    // pass 1: max
    float lmax = -3.4e38f;
    for (int i = tid; i < ncols; i += 256) lmax = fmaxf(lmax, row[i]);
    red[tid] = lmax;
    __syncthreads();
    for (int s = 128; s > 0; s >>= 1) {
        if (tid < s) red[tid] = fmaxf(red[tid], red[tid + s]);
        __syncthreads();
    }
    const float rmax = red[0];
    __syncthreads();

    // pass 2: exp + sum
    float lsum = 0.0f;
    for (int i = tid; i < ncols; i += 256) {
        float e = expf(row[i] - rmax);
        row[i] = e;
        lsum += e;
    }
    red[tid] = lsum;
    __syncthreads();
    for (int s = 128; s > 0; s >>= 1) {
        if (tid < s) red[tid] += red[tid + s];
        __syncthreads();
    }
    const float inv = 1.0f / red[0];
    __syncthreads();

    // pass 3: normalize
    for (int i = tid; i < ncols; i += 256) row[i] *= inv;
}

// ---------------------------------------------------------------------------
// kernel_launch
// inputs (metadata order): inputs, Wq, Wk, Wv, Wo, bo, scale
// output: [ output (B*S*D floats) | weights (B*S*S floats) ]
// ---------------------------------------------------------------------------
extern "C" void kernel_launch(void* const* d_in, const int* in_sizes, int n_in,
                              void* d_out, int out_size)
{
    const float* x     = (const float*)d_in[0];  // [B,S,D]
    const float* Wq    = (const float*)d_in[1];  // [D,U]
    const float* Wk    = (const float*)d_in[2];
    const float* Wv    = (const float*)d_in[3];
    const float* Wo    = (const float*)d_in[4];  // [U,D]
    const float* bo    = (const float*)d_in[5];  // [D]
    const float* scale = (const float*)d_in[6];  // scalar

    float* out  = (float*)d_out;                       // [B,S,D]
    float* wout = (float*)d_out + (long)BB * SS * DD;  // [B,S,S]

    float *q, *k, *v, *ctx;
    cudaGetSymbolAddress((void**)&q,   g_q);
    cudaGetSymbolAddress((void**)&k,   g_k);
    cudaGetSymbolAddress((void**)&v,   g_v);
    cudaGetSymbolAddress((void**)&ctx, g_ctx);

    const int M_all = BB * SS;  // 8192

    // --- QKV projections: [8192,1024] x [1024,1024] ---
    {
        dim3 grid(UU / BN, M_all / BM, 1);
        gemm_kernel<false, false, false><<<grid, 256>>>(
            x, Wq, q, M_all, UU, DD, 0, 0, 0, nullptr, nullptr);
        gemm_kernel<false, false, false><<<grid, 256>>>(
            x, Wk, k, M_all, UU, DD, 0, 0, 0, nullptr, nullptr);
        gemm_kernel<false, false, false><<<grid, 256>>>(
            x, Wv, v, M_all, UU, DD, 0, 0, 0, nullptr, nullptr);
    }

    // --- scores = scale * Q K^T, per batch: [2048,1024] x [2048,1024]^T ---
    {
        dim3 grid(SS / BN, SS / BM, BB);
        gemm_kernel<true, false, true><<<grid, 256>>>(
            q, k, wout, SS, SS, UU,
            (long)SS * UU, (long)SS * UU, (long)SS * SS, nullptr, scale);
    }

    // --- softmax rows (in place into weights output) ---
    softmax_rows<<<BB * SS, 256>>>(wout, SS);

    // --- context = weights @ V, per batch: [2048,2048] x [2048,1024] ---
    {
        dim3 grid(UU / BN, SS / BM, BB);
        gemm_kernel<false, false, false><<<grid, 256>>>(
            wout, v, ctx, SS, UU, SS,
            (long)SS * SS, (long)SS * UU, (long)SS * UU, nullptr, nullptr);
    }

    // --- output = ctx @ Wo + bo: [8192,1024] x [1024,1024] ---
    {
        dim3 grid(DD / BN, M_all / BM, 1);
        gemm_kernel<false, true, false><<<grid, 256>>>(
            ctx, Wo, out, M_all, DD, UU, 0, 0, 0, bo, nullptr);
    }

    (void)in_sizes; (void)n_in; (void)out_size;
}

// round 6
// speedup vs baseline: 2.2329x; 2.2329x over previous
#include <cuda_runtime.h>
#include <cstdint>

#define BB 4
#define SS 2048
#define DD 1024
#define UU 1024

// Scratch (static device globals; no runtime allocation allowed)
__device__ float g_q  [BB * SS * UU];
__device__ float g_k  [BB * SS * UU];
__device__ float g_vt [BB * UU * SS];   // V transposed per batch: [U, S]
__device__ float g_ctx[BB * SS * UU];
__device__ float g_wqt[UU * DD];
__device__ float g_wkt[UU * DD];
__device__ float g_wvt[UU * DD];
__device__ float g_wot[DD * UU];

__device__ __forceinline__ uint32_t f32_to_tf32(float x) {
    uint32_t r;
    asm("cvt.rna.tf32.f32 %0, %1;" : "=r"(r) : "f"(x));
    return r;
}

__device__ __forceinline__ void mma_tf32_16x8x8(float* c, const uint32_t* a, const uint32_t* b) {
    asm volatile(
        "mma.sync.aligned.m16n8k8.row.col.f32.tf32.tf32.f32 "
        "{%0,%1,%2,%3}, {%4,%5,%6,%7}, {%8,%9}, {%0,%1,%2,%3};"
        : "+f"(c[0]), "+f"(c[1]), "+f"(c[2]), "+f"(c[3])
        : "r"(a[0]), "r"(a[1]), "r"(a[2]), "r"(a[3]), "r"(b[0]), "r"(b[1]));
}

// ---------------------------------------------------------------------------
// tf32 mma.sync GEMM:  C[M,N] = alpha * A[M,K] * B[N,K]^T (+ bias[n])
// A, B row-major, K contiguous. CTA tile 128x128, BK=32, 256 threads.
// Warps 2(M) x 4(N); warp tile 64x32 = 4x4 grid of m16n8k8.
// SMEM tiles stored with pitch 36 floats -> fragment reads conflict-free.
// ---------------------------------------------------------------------------
#define PITCH 36
#define TILE_FLOATS (128 * PITCH)           // 4608
#define TILE_BYTES  (TILE_FLOATS * 4)       // 18432
#define SMEM_TOTAL  (4 * TILE_BYTES)        // A0, B0, A1, B1 = 73728

template <bool HASBIAS, bool HASALPHA>
__global__ void __launch_bounds__(256) tf32_gemm(
    const float* __restrict__ A, const float* __restrict__ B, float* __restrict__ C,
    int K, long lda, long ldb, long ldc,
    long sA, long sB, long sC,
    const float* __restrict__ bias, const float* __restrict__ alpha_ptr)
{
    extern __shared__ float smem[];
    float* bufA[2] = { smem,                  smem + 2 * TILE_FLOATS };
    float* bufB[2] = { smem + TILE_FLOATS,    smem + 3 * TILE_FLOATS };

    const int tid  = threadIdx.x;
    const int wid  = tid >> 5;
    const int lane = tid & 31;
    const int wm   = wid >> 2;          // 0..1
    const int wn   = wid & 3;           // 0..3
    const int gr   = lane >> 2;         // groupID 0..7
    const int gc   = lane & 3;          // 0..3

    A += (long)blockIdx.z * sA + (long)(blockIdx.y * 128) * lda;
    B += (long)blockIdx.z * sB + (long)(blockIdx.x * 128) * ldb;
    C += (long)blockIdx.z * sC;

    // Per-thread staging map: 4 float4 per operand tile.
    // linear = tid + 256*i  ->  row = linear>>3 (0..127), seg = linear&7 (16B seg)
    int srow[4], sseg[4];
#pragma unroll
    for (int i = 0; i < 4; ++i) {
        const int lin = tid + 256 * i;
        srow[i] = lin >> 3;
        sseg[i] = lin & 7;
    }

    float acc[4][4][4];
#pragma unroll
    for (int mt = 0; mt < 4; ++mt)
#pragma unroll
        for (int nt = 0; nt < 4; ++nt)
#pragma unroll
            for (int e = 0; e < 4; ++e) acc[mt][nt][e] = 0.0f;

    const int nch = K >> 5;   // K / 32

    float4 pa[4], pb[4];
    // prologue loads (chunk 0)
#pragma unroll
    for (int i = 0; i < 4; ++i) {
        pa[i] = *(const float4*)(A + (long)srow[i] * lda + sseg[i] * 4);
        pb[i] = *(const float4*)(B + (long)srow[i] * ldb + sseg[i] * 4);
    }

    // store chunk 0 into buffer 0 (with tf32 rounding)
#pragma unroll
    for (int i = 0; i < 4; ++i) {
        uint4 ta, tb;
        ta.x = f32_to_tf32(pa[i].x); ta.y = f32_to_tf32(pa[i].y);
        ta.z = f32_to_tf32(pa[i].z); ta.w = f32_to_tf32(pa[i].w);
        tb.x = f32_to_tf32(pb[i].x); tb.y = f32_to_tf32(pb[i].y);
        tb.z = f32_to_tf32(pb[i].z); tb.w = f32_to_tf32(pb[i].w);
        *(uint4*)(bufA[0] + srow[i] * PITCH + sseg[i] * 4) = ta;
        *(uint4*)(bufB[0] + srow[i] * PITCH + sseg[i] * 4) = tb;
    }
    __syncthreads();

    for (int c = 0; c < nch; ++c) {
        const int cur = c & 1;
        const bool more = (c + 1) < nch;

        if (more) {
            const float* An = A + (c + 1) * 32;
            const float* Bn = B + (c + 1) * 32;
#pragma unroll
            for (int i = 0; i < 4; ++i) {
                pa[i] = *(const float4*)(An + (long)srow[i] * lda + sseg[i] * 4);
                pb[i] = *(const float4*)(Bn + (long)srow[i] * ldb + sseg[i] * 4);
            }
        }

        const uint32_t* As = (const uint32_t*)bufA[cur];
        const uint32_t* Bs = (const uint32_t*)bufB[cur];

#pragma unroll
        for (int ks = 0; ks < 4; ++ks) {
            uint32_t af[4][4], bf[4][2];
#pragma unroll
            for (int mt = 0; mt < 4; ++mt) {
                const int base = (wm * 64 + mt * 16 + gr) * PITCH + ks * 8 + gc;
                af[mt][0] = As[base];
                af[mt][1] = As[base + 8 * PITCH];
                af[mt][2] = As[base + 4];
                af[mt][3] = As[base + 8 * PITCH + 4];
            }
#pragma unroll
            for (int nt = 0; nt < 4; ++nt) {
                const int base = (wn * 32 + nt * 8 + gr) * PITCH + ks * 8 + gc;
                bf[nt][0] = Bs[base];
                bf[nt][1] = Bs[base + 4];
            }
#pragma unroll
            for (int mt = 0; mt < 4; ++mt)
#pragma unroll
                for (int nt = 0; nt < 4; ++nt)
                    mma_tf32_16x8x8(acc[mt][nt], af[mt], bf[nt]);
        }

        if (more) {
            __syncthreads();   // all warps done reading buf[cur^1] in prior iter
            const int nxt = cur ^ 1;
#pragma unroll
            for (int i = 0; i < 4; ++i) {
                uint4 ta, tb;
                ta.x = f32_to_tf32(pa[i].x); ta.y = f32_to_tf32(pa[i].y);
                ta.z = f32_to_tf32(pa[i].z); ta.w = f32_to_tf32(pa[i].w);
                tb.x = f32_to_tf32(pb[i].x); tb.y = f32_to_tf32(pb[i].y);
                tb.z = f32_to_tf32(pb[i].z); tb.w = f32_to_tf32(pb[i].w);
                *(uint4*)(bufA[nxt] + srow[i] * PITCH + sseg[i] * 4) = ta;
                *(uint4*)(bufB[nxt] + srow[i] * PITCH + sseg[i] * 4) = tb;
            }
            __syncthreads();
        }
    }

    // Epilogue
    const float alpha = HASALPHA ? *alpha_ptr : 1.0f;
    const int row_base = blockIdx.y * 128 + wm * 64;
    const int col_base = blockIdx.x * 128 + wn * 32;

#pragma unroll
    for (int mt = 0; mt < 4; ++mt) {
#pragma unroll
        for (int nt = 0; nt < 4; ++nt) {
            const int r0 = row_base + mt * 16 + gr;
            const int cc = col_base + nt * 8 + 2 * gc;
            float2 v0, v1;
            v0.x = acc[mt][nt][0] * alpha;
            v0.y = acc[mt][nt][1] * alpha;
            v1.x = acc[mt][nt][2] * alpha;
            v1.y = acc[mt][nt][3] * alpha;
            if (HASBIAS) {
                const float2 bv = *(const float2*)(bias + cc);
                v0.x += bv.x; v0.y += bv.y;
                v1.x += bv.x; v1.y += bv.y;
            }
            *(float2*)(C + (long)r0 * ldc + cc)       = v0;
            *(float2*)(C + (long)(r0 + 8) * ldc + cc) = v1;
        }
    }
}

// ---------------------------------------------------------------------------
// 32x32 tiled transpose: out[C x R] = in[R x C]^T
// ---------------------------------------------------------------------------
__global__ void __launch_bounds__(256) transpose_k(
    const float* __restrict__ in, float* __restrict__ out, int R, int C)
{
    __shared__ float t[32][33];
    const int bx = blockIdx.x * 32, by = blockIdx.y * 32;
    const int txx = threadIdx.x, tyy = threadIdx.y;
#pragma unroll
    for (int i = 0; i < 4; ++i)
        t[tyy + 8 * i][txx] = in[(long)(by + tyy + 8 * i) * C + bx + txx];
    __syncthreads();
#pragma unroll
    for (int i = 0; i < 4; ++i)
        out[(long)(bx + tyy + 8 * i) * R + by + txx] = t[txx][tyy + 8 * i];
}

// ---------------------------------------------------------------------------
// Single-pass softmax over rows of 2048. 256 threads, 8 values/thread in regs.
// ---------------------------------------------------------------------------
__global__ void __launch_bounds__(256) softmax2048(float* __restrict__ data)
{
    __shared__ float red[8];
    float* row = data + (long)blockIdx.x * 2048;
    const int tid = threadIdx.x;

    float v[8];
    float m = -3.4e38f;
#pragma unroll
    for (int i = 0; i < 8; ++i) { v[i] = row[tid + 256 * i]; m = fmaxf(m, v[i]); }
#pragma unroll
    for (int s = 16; s > 0; s >>= 1) m = fmaxf(m, __shfl_xor_sync(0xFFFFFFFF, m, s));
    if ((tid & 31) == 0) red[tid >> 5] = m;
    __syncthreads();
    m = red[tid & 7];
#pragma unroll
    for (int s = 4; s > 0; s >>= 1) m = fmaxf(m, __shfl_xor_sync(0xFFFFFFFF, m, s));
    __syncthreads();

    float sum = 0.0f;
#pragma unroll
    for (int i = 0; i < 8; ++i) { v[i] = __expf(v[i] - m); sum += v[i]; }
#pragma unroll
    for (int s = 16; s > 0; s >>= 1) sum += __shfl_xor_sync(0xFFFFFFFF, sum, s);
    if ((tid & 31) == 0) red[tid >> 5] = sum;
    __syncthreads();
    sum = red[tid & 7];
#pragma unroll
    for (int s = 4; s > 0; s >>= 1) sum += __shfl_xor_sync(0xFFFFFFFF, sum, s);

    const float inv = 1.0f / sum;
#pragma unroll
    for (int i = 0; i < 8; ++i) row[tid + 256 * i] = v[i] * inv;
}

// ---------------------------------------------------------------------------
// kernel_launch
// inputs: inputs[B,S,D], Wq[D,U], Wk[D,U], Wv[D,U], Wo[U,D], bo[D], scale
// output: [ output (B*S*D) | weights (B*S*S) ]
// ---------------------------------------------------------------------------
extern "C" void kernel_launch(void* const* d_in, const int* in_sizes, int n_in,
                              void* d_out, int out_size)
{
    const float* x     = (const float*)d_in[0];
    const float* Wq    = (const float*)d_in[1];
    const float* Wk    = (const float*)d_in[2];
    const float* Wv    = (const float*)d_in[3];
    const float* Wo    = (const float*)d_in[4];
    const float* bo    = (const float*)d_in[5];
    const float* scale = (const float*)d_in[6];

    float* out  = (float*)d_out;
    float* wout = (float*)d_out + (long)BB * SS * DD;

    float *q, *k, *vt, *ctx, *wqt, *wkt, *wvt, *wot;
    cudaGetSymbolAddress((void**)&q,   g_q);
    cudaGetSymbolAddress((void**)&k,   g_k);
    cudaGetSymbolAddress((void**)&vt,  g_vt);
    cudaGetSymbolAddress((void**)&ctx, g_ctx);
    cudaGetSymbolAddress((void**)&wqt, g_wqt);
    cudaGetSymbolAddress((void**)&wkt, g_wkt);
    cudaGetSymbolAddress((void**)&wvt, g_wvt);
    cudaGetSymbolAddress((void**)&wot, g_wot);

    cudaFuncSetAttribute(tf32_gemm<false, false>,
                         cudaFuncAttributeMaxDynamicSharedMemorySize, SMEM_TOTAL);
    cudaFuncSetAttribute(tf32_gemm<false, true>,
                         cudaFuncAttributeMaxDynamicSharedMemorySize, SMEM_TOTAL);
    cudaFuncSetAttribute(tf32_gemm<true, false>,
                         cudaFuncAttributeMaxDynamicSharedMemorySize, SMEM_TOTAL);

    // 1) Transpose weights (B operand must be [N, K], K contiguous)
    {
        dim3 blk(32, 8);
        transpose_k<<<dim3(UU / 32, DD / 32), blk>>>(Wq, wqt, DD, UU);
        transpose_k<<<dim3(UU / 32, DD / 32), blk>>>(Wk, wkt, DD, UU);
        transpose_k<<<dim3(UU / 32, DD / 32), blk>>>(Wv, wvt, DD, UU);
        transpose_k<<<dim3(DD / 32, UU / 32), blk>>>(Wo, wot, UU, DD);
    }

    const int M_all = BB * SS;  // 8192

    // 2) Q = X @ Wq
    tf32_gemm<false, false><<<dim3(UU / 128, M_all / 128, 1), 256, SMEM_TOTAL>>>(
        x, wqt, q, DD, DD, DD, UU, 0, 0, 0, nullptr, nullptr);
    // 3) K = X @ Wk
    tf32_gemm<false, false><<<dim3(UU / 128, M_all / 128, 1), 256, SMEM_TOTAL>>>(
        x, wkt, k, DD, DD, DD, UU, 0, 0, 0, nullptr, nullptr);
    // 4) Vt[b] = (X_b @ Wv)^T : A=Wvt [U,D], B=X_b [S,D], C=Vt_b [U,S]
    tf32_gemm<false, false><<<dim3(SS / 128, UU / 128, BB), 256, SMEM_TOTAL>>>(
        wvt, x, vt, DD, DD, DD, SS,
        0, (long)SS * DD, (long)UU * SS, nullptr, nullptr);
    // 5) scores[b] = scale * Q_b @ K_b^T
    tf32_gemm<false, true><<<dim3(SS / 128, SS / 128, BB), 256, SMEM_TOTAL>>>(
        q, k, wout, UU, UU, UU, SS,
        (long)SS * UU, (long)SS * UU, (long)SS * SS, nullptr, scale);
    // 6) softmax rows (in place, weights output)
    softmax2048<<<BB * SS, 256>>>(wout);
    // 7) ctx[b] = weights_b @ V_b : A=wout_b [S,S], B=Vt_b [U,S]
    tf32_gemm<false, false><<<dim3(UU / 128, SS / 128, BB), 256, SMEM_TOTAL>>>(
        wout, vt, ctx, SS, SS, SS, UU,
        (long)SS * SS, (long)UU * SS, (long)SS * UU, nullptr, nullptr);
    // 8) out = ctx @ Wo + bo
    tf32_gemm<true, false><<<dim3(DD / 128, M_all / 128, 1), 256, SMEM_TOTAL>>>(
        ctx, wot, out, UU, UU, UU, DD, 0, 0, 0, bo, nullptr);

    (void)in_sizes; (void)n_in; (void)out_size;
}

// round 8
// speedup vs baseline: 3.0610x; 1.3708x over previous
#include <cuda_runtime.h>
#include <cstdint>

#define BB 4
#define SS 2048
#define DD 1024
#define UU 1024

// Scratch (static device globals; no runtime allocation allowed)
__device__ float g_q  [BB * SS * UU];
__device__ float g_k  [BB * SS * UU];
__device__ float g_vt [BB * UU * SS];   // V transposed per batch: [U, S]
__device__ float g_ctx[BB * SS * UU];
__device__ float g_wqt[UU * DD];
__device__ float g_wkt[UU * DD];
__device__ float g_wvt[UU * DD];
__device__ float g_wot[DD * UU];

__device__ __forceinline__ uint32_t f32_to_tf32(float x) {
    uint32_t r;
    asm("cvt.rna.tf32.f32 %0, %1;" : "=r"(r) : "f"(x));
    return r;
}

__device__ __forceinline__ uint32_t smem_u32(const void* p) {
    uint32_t a;
    asm("{ .reg .u64 t; cvta.to.shared.u64 t, %1; cvt.u32.u64 %0, t; }" : "=r"(a) : "l"(p));
    return a;
}

__device__ __forceinline__ void ldsm_x4(uint32_t& r0, uint32_t& r1, uint32_t& r2, uint32_t& r3,
                                        uint32_t addr) {
    asm volatile("ldmatrix.sync.aligned.m8n8.x4.shared.b16 {%0,%1,%2,%3}, [%4];"
                 : "=r"(r0), "=r"(r1), "=r"(r2), "=r"(r3) : "r"(addr));
}

__device__ __forceinline__ void mma_tf32_16x8x8(float* c, const uint32_t* a, const uint32_t* b) {
    asm volatile(
        "mma.sync.aligned.m16n8k8.row.col.f32.tf32.tf32.f32 "
        "{%0,%1,%2,%3}, {%4,%5,%6,%7}, {%8,%9}, {%0,%1,%2,%3};"
        : "+f"(c[0]), "+f"(c[1]), "+f"(c[2]), "+f"(c[3])
        : "r"(a[0]), "r"(a[1]), "r"(a[2]), "r"(a[3]), "r"(b[0]), "r"(b[1]));
}

// ---------------------------------------------------------------------------
// tf32 mma.sync GEMM:  C[M,N] = alpha * A[M,K] * B[N,K]^T (+ bias[n])
// A, B row-major, K contiguous. CTA tile 128x128, BK=32, 256 threads.
// Warps 2(M) x 4(N); warp tile 64x32 = 4x4 grid of m16n8k8.
// Fragments fed via ldmatrix.x4 (tf32-as-b16-pairs trick).
// SMEM tiles stored with pitch 36 floats -> LDSM / staging conflict-free.
// ---------------------------------------------------------------------------
#define PITCH 36
#define TILE_FLOATS (128 * PITCH)           // 4608
#define TILE_BYTES  (TILE_FLOATS * 4)       // 18432
#define SMEM_TOTAL  (4 * TILE_BYTES)        // A0, B0, A1, B1 = 73728

template <bool HASBIAS, bool HASALPHA>
__global__ void __launch_bounds__(256) tf32_gemm(
    const float* __restrict__ A, const float* __restrict__ B, float* __restrict__ C,
    int K, long lda, long ldb, long ldc,
    long sA, long sB, long sC,
    const float* __restrict__ bias, const float* __restrict__ alpha_ptr)
{
    extern __shared__ float smem[];
    float* bufA[2] = { smem,                  smem + 2 * TILE_FLOATS };
    float* bufB[2] = { smem + TILE_FLOATS,    smem + 3 * TILE_FLOATS };

    const uint32_t smem32 = smem_u32(smem);
    const uint32_t aAddr[2] = { smem32,                  smem32 + 2u * TILE_BYTES };
    const uint32_t bAddr[2] = { smem32 + 1u * TILE_BYTES, smem32 + 3u * TILE_BYTES };

    const int tid  = threadIdx.x;
    const int wid  = tid >> 5;
    const int lane = tid & 31;
    const int wm   = wid >> 2;          // 0..1
    const int wn   = wid & 3;           // 0..3
    const int gr   = lane >> 2;         // groupID 0..7
    const int gc   = lane & 3;          // 0..3

    A += (long)blockIdx.z * sA + (long)(blockIdx.y * 128) * lda;
    B += (long)blockIdx.z * sB + (long)(blockIdx.x * 128) * ldb;
    C += (long)blockIdx.z * sC;

    // ldmatrix per-lane source offsets (float elements within tile).
    // A, per mt: x4 covers {rows+0/+8} x {k+0/+4}:
    //   q = lane>>3 : m0(q=0): +0,+0  m1(q=1): +8,+0  m2(q=2): +0,+4  m3(q=3): +8,+4
    const int q  = lane >> 3;
    const int rr = lane & 7;
    uint32_t offA[4], offB[2];
#pragma unroll
    for (int mt = 0; mt < 4; ++mt)
        offA[mt] = (uint32_t)((wm * 64 + mt * 16 + (q & 1) * 8 + rr) * PITCH + (q >> 1) * 4) * 4u;
    // B, per pair p (nt=2p, 2p+1): m0: rows+0,k+0  m1: rows+0,k+4  m2: rows+8,k+0  m3: rows+8,k+4
#pragma unroll
    for (int p = 0; p < 2; ++p)
        offB[p] = (uint32_t)((wn * 32 + p * 16 + (q >> 1) * 8 + rr) * PITCH + (q & 1) * 4) * 4u;

    // Per-thread staging map: 4 float4 per operand tile.
    int srow[4], sseg[4];
#pragma unroll
    for (int i = 0; i < 4; ++i) {
        const int lin = tid + 256 * i;
        srow[i] = lin >> 3;
        sseg[i] = lin & 7;
    }

    float acc[4][4][4];
#pragma unroll
    for (int mt = 0; mt < 4; ++mt)
#pragma unroll
        for (int nt = 0; nt < 4; ++nt)
#pragma unroll
            for (int e = 0; e < 4; ++e) acc[mt][nt][e] = 0.0f;

    const int nch = K >> 5;   // K / 32

    float4 pa[4], pb[4];
#pragma unroll
    for (int i = 0; i < 4; ++i) {
        pa[i] = *(const float4*)(A + (long)srow[i] * lda + sseg[i] * 4);
        pb[i] = *(const float4*)(B + (long)srow[i] * ldb + sseg[i] * 4);
    }
#pragma unroll
    for (int i = 0; i < 4; ++i) {
        uint4 ta, tb;
        ta.x = f32_to_tf32(pa[i].x); ta.y = f32_to_tf32(pa[i].y);
        ta.z = f32_to_tf32(pa[i].z); ta.w = f32_to_tf32(pa[i].w);
        tb.x = f32_to_tf32(pb[i].x); tb.y = f32_to_tf32(pb[i].y);
        tb.z = f32_to_tf32(pb[i].z); tb.w = f32_to_tf32(pb[i].w);
        *(uint4*)(bufA[0] + srow[i] * PITCH + sseg[i] * 4) = ta;
        *(uint4*)(bufB[0] + srow[i] * PITCH + sseg[i] * 4) = tb;
    }
    __syncthreads();

    for (int c = 0; c < nch; ++c) {
        const int cur = c & 1;
        const bool more = (c + 1) < nch;

        if (more) {
            const float* An = A + (c + 1) * 32;
            const float* Bn = B + (c + 1) * 32;
#pragma unroll
            for (int i = 0; i < 4; ++i) {
                pa[i] = *(const float4*)(An + (long)srow[i] * lda + sseg[i] * 4);
                pb[i] = *(const float4*)(Bn + (long)srow[i] * ldb + sseg[i] * 4);
            }
        }

        const uint32_t aB = aAddr[cur];
        const uint32_t bB = bAddr[cur];

#pragma unroll
        for (int ks = 0; ks < 4; ++ks) {
            uint32_t af[4][4], bf[4][2];
#pragma unroll
            for (int mt = 0; mt < 4; ++mt)
                ldsm_x4(af[mt][0], af[mt][1], af[mt][2], af[mt][3],
                        aB + offA[mt] + ks * 32u);
#pragma unroll
            for (int p = 0; p < 2; ++p)
                ldsm_x4(bf[2 * p][0], bf[2 * p][1], bf[2 * p + 1][0], bf[2 * p + 1][1],
                        bB + offB[p] + ks * 32u);
#pragma unroll
            for (int mt = 0; mt < 4; ++mt)
#pragma unroll
                for (int nt = 0; nt < 4; ++nt)
                    mma_tf32_16x8x8(acc[mt][nt], af[mt], bf[nt]);
        }

        if (more) {
            __syncthreads();
            const int nxt = cur ^ 1;
#pragma unroll
            for (int i = 0; i < 4; ++i) {
                uint4 ta, tb;
                ta.x = f32_to_tf32(pa[i].x); ta.y = f32_to_tf32(pa[i].y);
                ta.z = f32_to_tf32(pa[i].z); ta.w = f32_to_tf32(pa[i].w);
                tb.x = f32_to_tf32(pb[i].x); tb.y = f32_to_tf32(pb[i].y);
                tb.z = f32_to_tf32(pb[i].z); tb.w = f32_to_tf32(pb[i].w);
                *(uint4*)(bufA[nxt] + srow[i] * PITCH + sseg[i] * 4) = ta;
                *(uint4*)(bufB[nxt] + srow[i] * PITCH + sseg[i] * 4) = tb;
            }
            __syncthreads();
        }
    }

    // Epilogue
    const float alpha = HASALPHA ? *alpha_ptr : 1.0f;
    const int row_base = blockIdx.y * 128 + wm * 64;
    const int col_base = blockIdx.x * 128 + wn * 32;

#pragma unroll
    for (int mt = 0; mt < 4; ++mt) {
#pragma unroll
        for (int nt = 0; nt < 4; ++nt) {
            const int r0 = row_base + mt * 16 + gr;
            const int cc = col_base + nt * 8 + 2 * gc;
            float2 v0, v1;
            v0.x = acc[mt][nt][0] * alpha;
            v0.y = acc[mt][nt][1] * alpha;
            v1.x = acc[mt][nt][2] * alpha;
            v1.y = acc[mt][nt][3] * alpha;
            if (HASBIAS) {
                const float2 bv = *(const float2*)(bias + cc);
                v0.x += bv.x; v0.y += bv.y;
                v1.x += bv.x; v1.y += bv.y;
            }
            *(float2*)(C + (long)r0 * ldc + cc)       = v0;
            *(float2*)(C + (long)(r0 + 8) * ldc + cc) = v1;
        }
    }
}

// ---------------------------------------------------------------------------
// 32x32 tiled transpose: out[C x R] = in[R x C]^T
// ---------------------------------------------------------------------------
__global__ void __launch_bounds__(256) transpose_k(
    const float* __restrict__ in, float* __restrict__ out, int R, int C)
{
    __shared__ float t[32][33];
    const int bx = blockIdx.x * 32, by = blockIdx.y * 32;
    const int txx = threadIdx.x, tyy = threadIdx.y;
#pragma unroll
    for (int i = 0; i < 4; ++i)
        t[tyy + 8 * i][txx] = in[(long)(by + tyy + 8 * i) * C + bx + txx];
    __syncthreads();
#pragma unroll
    for (int i = 0; i < 4; ++i)
        out[(long)(bx + tyy + 8 * i) * R + by + txx] = t[txx][tyy + 8 * i];
}

// ---------------------------------------------------------------------------
// Single-pass softmax over rows of 2048. 256 threads, 8 values/thread in regs.
// ---------------------------------------------------------------------------
__global__ void __launch_bounds__(256) softmax2048(float* __restrict__ data)
{
    __shared__ float red[8];
    float* row = data + (long)blockIdx.x * 2048;
    const int tid = threadIdx.x;

    float v[8];
    float m = -3.4e38f;
#pragma unroll
    for (int i = 0; i < 8; ++i) { v[i] = row[tid + 256 * i]; m = fmaxf(m, v[i]); }
#pragma unroll
    for (int s = 16; s > 0; s >>= 1) m = fmaxf(m, __shfl_xor_sync(0xFFFFFFFF, m, s));
    if ((tid & 31) == 0) red[tid >> 5] = m;
    __syncthreads();
    m = red[tid & 7];
#pragma unroll
    for (int s = 4; s > 0; s >>= 1) m = fmaxf(m, __shfl_xor_sync(0xFFFFFFFF, m, s));
    __syncthreads();

    float sum = 0.0f;
#pragma unroll
    for (int i = 0; i < 8; ++i) { v[i] = __expf(v[i] - m); sum += v[i]; }
#pragma unroll
    for (int s = 16; s > 0; s >>= 1) sum += __shfl_xor_sync(0xFFFFFFFF, sum, s);
    if ((tid & 31) == 0) red[tid >> 5] = sum;
    __syncthreads();
    sum = red[tid & 7];
#pragma unroll
    for (int s = 4; s > 0; s >>= 1) sum += __shfl_xor_sync(0xFFFFFFFF, sum, s);

    const float inv = 1.0f / sum;
#pragma unroll
    for (int i = 0; i < 8; ++i) row[tid + 256 * i] = v[i] * inv;
}

// ---------------------------------------------------------------------------
// kernel_launch
// inputs: inputs[B,S,D], Wq[D,U], Wk[D,U], Wv[D,U], Wo[U,D], bo[D], scale
// output: [ output (B*S*D) | weights (B*S*S) ]
// ---------------------------------------------------------------------------
extern "C" void kernel_launch(void* const* d_in, const int* in_sizes, int n_in,
                              void* d_out, int out_size)
{
    const float* x     = (const float*)d_in[0];
    const float* Wq    = (const float*)d_in[1];
    const float* Wk    = (const float*)d_in[2];
    const float* Wv    = (const float*)d_in[3];
    const float* Wo    = (const float*)d_in[4];
    const float* bo    = (const float*)d_in[5];
    const float* scale = (const float*)d_in[6];

    float* out  = (float*)d_out;
    float* wout = (float*)d_out + (long)BB * SS * DD;

    float *q, *k, *vt, *ctx, *wqt, *wkt, *wvt, *wot;
    cudaGetSymbolAddress((void**)&q,   g_q);
    cudaGetSymbolAddress((void**)&k,   g_k);
    cudaGetSymbolAddress((void**)&vt,  g_vt);
    cudaGetSymbolAddress((void**)&ctx, g_ctx);
    cudaGetSymbolAddress((void**)&wqt, g_wqt);
    cudaGetSymbolAddress((void**)&wkt, g_wkt);
    cudaGetSymbolAddress((void**)&wvt, g_wvt);
    cudaGetSymbolAddress((void**)&wot, g_wot);

    cudaFuncSetAttribute(tf32_gemm<false, false>,
                         cudaFuncAttributeMaxDynamicSharedMemorySize, SMEM_TOTAL);
    cudaFuncSetAttribute(tf32_gemm<false, true>,
                         cudaFuncAttributeMaxDynamicSharedMemorySize, SMEM_TOTAL);
    cudaFuncSetAttribute(tf32_gemm<true, false>,
                         cudaFuncAttributeMaxDynamicSharedMemorySize, SMEM_TOTAL);

    // 1) Transpose weights (B operand must be [N, K], K contiguous)
    {
        dim3 blk(32, 8);
        transpose_k<<<dim3(UU / 32, DD / 32), blk>>>(Wq, wqt, DD, UU);
        transpose_k<<<dim3(UU / 32, DD / 32), blk>>>(Wk, wkt, DD, UU);
        transpose_k<<<dim3(UU / 32, DD / 32), blk>>>(Wv, wvt, DD, UU);
        transpose_k<<<dim3(DD / 32, UU / 32), blk>>>(Wo, wot, UU, DD);
    }

    const int M_all = BB * SS;  // 8192

    // 2) Q = X @ Wq
    tf32_gemm<false, false><<<dim3(UU / 128, M_all / 128, 1), 256, SMEM_TOTAL>>>(
        x, wqt, q, DD, DD, DD, UU, 0, 0, 0, nullptr, nullptr);
    // 3) K = X @ Wk
    tf32_gemm<false, false><<<dim3(UU / 128, M_all / 128, 1), 256, SMEM_TOTAL>>>(
        x, wkt, k, DD, DD, DD, UU, 0, 0, 0, nullptr, nullptr);
    // 4) Vt[b] = (X_b @ Wv)^T : A=Wvt [U,D], B=X_b [S,D], C=Vt_b [U,S]
    tf32_gemm<false, false><<<dim3(SS / 128, UU / 128, BB), 256, SMEM_TOTAL>>>(
        wvt, x, vt, DD, DD, DD, SS,
        0, (long)SS * DD, (long)UU * SS, nullptr, nullptr);
    // 5) scores[b] = scale * Q_b @ K_b^T
    tf32_gemm<false, true><<<dim3(SS / 128, SS / 128, BB), 256, SMEM_TOTAL>>>(
        q, k, wout, UU, UU, UU, SS,
        (long)SS * UU, (long)SS * UU, (long)SS * SS, nullptr, scale);
    // 6) softmax rows (in place, weights output)
    softmax2048<<<BB * SS, 256>>>(wout);
    // 7) ctx[b] = weights_b @ V_b : A=wout_b [S,S], B=Vt_b [U,S]
    tf32_gemm<false, false><<<dim3(UU / 128, SS / 128, BB), 256, SMEM_TOTAL>>>(
        wout, vt, ctx, SS, SS, SS, UU,
        (long)SS * SS, (long)UU * SS, (long)SS * UU, nullptr, nullptr);
    // 8) out = ctx @ Wo + bo
    tf32_gemm<true, false><<<dim3(DD / 128, M_all / 128, 1), 256, SMEM_TOTAL>>>(
        ctx, wot, out, UU, UU, UU, DD, 0, 0, 0, bo, nullptr);

    (void)in_sizes; (void)n_in; (void)out_size;
}

// round 9
// speedup vs baseline: 4.1228x; 1.3469x over previous
#include <cuda_runtime.h>
#include <cstdint>

#define BB 4
#define SS 2048
#define DD 1024
#define UU 1024

// Scratch (static device globals; no runtime allocation allowed)
__device__ float g_q  [BB * SS * UU];
__device__ float g_k  [BB * SS * UU];
__device__ float g_vt [BB * UU * SS];   // V transposed per batch: [U, S]
__device__ float g_ctx[BB * SS * UU];   // also aliased as rounded-X before GEMM 7
__device__ float g_wr [BB * SS * SS];   // tf32-rounded softmax weights
__device__ float g_wqt[UU * DD];
__device__ float g_wkt[UU * DD];
__device__ float g_wvt[UU * DD];
__device__ float g_wot[DD * UU];

__device__ __forceinline__ uint32_t f32_to_tf32(float x) {
    uint32_t r;
    asm("cvt.rna.tf32.f32 %0, %1;" : "=r"(r) : "f"(x));
    return r;
}
__device__ __forceinline__ float round_tf32(float x) {
    return __uint_as_float(f32_to_tf32(x));
}

__device__ __forceinline__ uint32_t smem_u32(const void* p) {
    uint32_t a;
    asm("{ .reg .u64 t; cvta.to.shared.u64 t, %1; cvt.u32.u64 %0, t; }" : "=r"(a) : "l"(p));
    return a;
}

__device__ __forceinline__ void cp16(uint32_t dst, const float* src) {
    asm volatile("cp.async.cg.shared.global [%0], [%1], 16;" :: "r"(dst), "l"(src));
}
#define CP_COMMIT()  asm volatile("cp.async.commit_group;" ::: "memory")
#define CP_WAIT1()   asm volatile("cp.async.wait_group 1;" ::: "memory")

__device__ __forceinline__ void ldsm_x4(uint32_t& r0, uint32_t& r1, uint32_t& r2, uint32_t& r3,
                                        uint32_t addr) {
    asm volatile("ldmatrix.sync.aligned.m8n8.x4.shared.b16 {%0,%1,%2,%3}, [%4];"
                 : "=r"(r0), "=r"(r1), "=r"(r2), "=r"(r3) : "r"(addr));
}

__device__ __forceinline__ void mma_tf32_16x8x8(float* c, const uint32_t* a, const uint32_t* b) {
    asm volatile(
        "mma.sync.aligned.m16n8k8.row.col.f32.tf32.tf32.f32 "
        "{%0,%1,%2,%3}, {%4,%5,%6,%7}, {%8,%9}, {%0,%1,%2,%3};"
        : "+f"(c[0]), "+f"(c[1]), "+f"(c[2]), "+f"(c[3])
        : "r"(a[0]), "r"(a[1]), "r"(a[2]), "r"(a[3]), "r"(b[0]), "r"(b[1]));
}

// ---------------------------------------------------------------------------
// tf32 mma.sync GEMM:  C[M,N] = alpha * A[M,K] * B[N,K]^T (+ bias[n])
// Inputs must already be tf32-rounded fp32. CTA tile 128x128, BK=32,
// 256 threads, warps 2(M)x4(N), warp tile 64x32 (4x4 m16n8k8).
// 3-stage cp.async pipeline, ldmatrix fragment feeding, pitch-36 SMEM rows.
// ---------------------------------------------------------------------------
#define PITCH 36
#define TILE_FLOATS (128 * PITCH)           // 4608
#define TILE_BYTES  (TILE_FLOATS * 4)       // 18432
#define STAGES 3
#define SMEM_TOTAL  (STAGES * 2 * TILE_BYTES)   // 110592

template <bool HASBIAS, bool HASALPHA, bool ROUNDOUT>
__global__ void __launch_bounds__(256) tf32_gemm(
    const float* __restrict__ A, const float* __restrict__ B, float* __restrict__ C,
    int K, long lda, long ldb, long ldc,
    long sA, long sB, long sC,
    const float* __restrict__ bias, const float* __restrict__ alpha_ptr)
{
    extern __shared__ float smem[];
    const uint32_t smem32 = smem_u32(smem);

    const int tid  = threadIdx.x;
    const int wid  = tid >> 5;
    const int lane = tid & 31;
    const int wm   = wid >> 2;          // 0..1
    const int wn   = wid & 3;           // 0..3
    const int gr   = lane >> 2;         // 0..7
    const int gc   = lane & 3;          // 0..3

    A += (long)blockIdx.z * sA + (long)(blockIdx.y * 128) * lda;
    B += (long)blockIdx.z * sB + (long)(blockIdx.x * 128) * ldb;
    C += (long)blockIdx.z * sC;

    // ldmatrix per-lane source offsets (bytes within a tile)
    const int q  = lane >> 3;
    const int rr = lane & 7;
    uint32_t offA[4], offB[2];
#pragma unroll
    for (int mt = 0; mt < 4; ++mt)
        offA[mt] = (uint32_t)((wm * 64 + mt * 16 + (q & 1) * 8 + rr) * PITCH + (q >> 1) * 4) * 4u;
#pragma unroll
    for (int p = 0; p < 2; ++p)
        offB[p] = (uint32_t)((wn * 32 + p * 16 + (q >> 1) * 8 + rr) * PITCH + (q & 1) * 4) * 4u;

    // staging map: 4 x 16B per operand per chunk per thread
    int srow[4], sseg[4];
#pragma unroll
    for (int i = 0; i < 4; ++i) {
        const int lin = tid + 256 * i;
        srow[i] = lin >> 3;
        sseg[i] = lin & 7;
    }

    uint32_t aAddr[STAGES], bAddr[STAGES];
#pragma unroll
    for (int s = 0; s < STAGES; ++s) {
        aAddr[s] = smem32 + (uint32_t)(s * 2) * TILE_BYTES;
        bAddr[s] = aAddr[s] + TILE_BYTES;
    }

    float acc[4][4][4];
#pragma unroll
    for (int mt = 0; mt < 4; ++mt)
#pragma unroll
        for (int nt = 0; nt < 4; ++nt)
#pragma unroll
            for (int e = 0; e < 4; ++e) acc[mt][nt][e] = 0.0f;

    const int nch = K >> 5;

    // issue chunk -> stage
    auto issue = [&](int chunk, int stage) {
        const float* An = A + chunk * 32;
        const float* Bn = B + chunk * 32;
#pragma unroll
        for (int i = 0; i < 4; ++i) {
            const uint32_t so = (uint32_t)(srow[i] * PITCH + sseg[i] * 4) * 4u;
            cp16(aAddr[stage] + so, An + (long)srow[i] * lda + sseg[i] * 4);
            cp16(bAddr[stage] + so, Bn + (long)srow[i] * ldb + sseg[i] * 4);
        }
    };

    // prologue: chunks 0,1 into stages 0,1
    issue(0, 0);
    CP_COMMIT();
    if (nch > 1) issue(1, 1);
    CP_COMMIT();

    for (int c = 0; c < nch; ++c) {
        CP_WAIT1();              // chunk c arrived (<=1 group pending)
        __syncthreads();         // all threads' copies visible

        if (c + 2 < nch) issue(c + 2, (c + 2) % STAGES);
        CP_COMMIT();

        const int st = c % STAGES;
        const uint32_t aB = aAddr[st];
        const uint32_t bB = bAddr[st];

#pragma unroll
        for (int ks = 0; ks < 4; ++ks) {
            uint32_t af[4][4], bf[4][2];
#pragma unroll
            for (int mt = 0; mt < 4; ++mt)
                ldsm_x4(af[mt][0], af[mt][1], af[mt][2], af[mt][3],
                        aB + offA[mt] + ks * 32u);
#pragma unroll
            for (int p = 0; p < 2; ++p)
                ldsm_x4(bf[2 * p][0], bf[2 * p][1], bf[2 * p + 1][0], bf[2 * p + 1][1],
                        bB + offB[p] + ks * 32u);
#pragma unroll
            for (int mt = 0; mt < 4; ++mt)
#pragma unroll
                for (int nt = 0; nt < 4; ++nt)
                    mma_tf32_16x8x8(acc[mt][nt], af[mt], bf[nt]);
        }
    }

    // Epilogue
    const float alpha = HASALPHA ? *alpha_ptr : 1.0f;
    const int row_base = blockIdx.y * 128 + wm * 64;
    const int col_base = blockIdx.x * 128 + wn * 32;

#pragma unroll
    for (int mt = 0; mt < 4; ++mt) {
#pragma unroll
        for (int nt = 0; nt < 4; ++nt) {
            const int r0 = row_base + mt * 16 + gr;
            const int cc = col_base + nt * 8 + 2 * gc;
            float2 v0, v1;
            v0.x = acc[mt][nt][0] * alpha;
            v0.y = acc[mt][nt][1] * alpha;
            v1.x = acc[mt][nt][2] * alpha;
            v1.y = acc[mt][nt][3] * alpha;
            if (HASBIAS) {
                const float2 bv = *(const float2*)(bias + cc);
                v0.x += bv.x; v0.y += bv.y;
                v1.x += bv.x; v1.y += bv.y;
            }
            if (ROUNDOUT) {
                v0.x = round_tf32(v0.x); v0.y = round_tf32(v0.y);
                v1.x = round_tf32(v1.x); v1.y = round_tf32(v1.y);
            }
            *(float2*)(C + (long)r0 * ldc + cc)       = v0;
            *(float2*)(C + (long)(r0 + 8) * ldc + cc) = v1;
        }
    }
}

// ---------------------------------------------------------------------------
// 32x32 tiled transpose with tf32 rounding: out[C x R] = round(in[R x C]^T)
// ---------------------------------------------------------------------------
__global__ void __launch_bounds__(256) transpose_k(
    const float* __restrict__ in, float* __restrict__ out, int R, int C)
{
    __shared__ float t[32][33];
    const int bx = blockIdx.x * 32, by = blockIdx.y * 32;
    const int txx = threadIdx.x, tyy = threadIdx.y;
#pragma unroll
    for (int i = 0; i < 4; ++i)
        t[tyy + 8 * i][txx] = in[(long)(by + tyy + 8 * i) * C + bx + txx];
    __syncthreads();
#pragma unroll
    for (int i = 0; i < 4; ++i)
        out[(long)(bx + tyy + 8 * i) * R + by + txx] = round_tf32(t[txx][tyy + 8 * i]);
}

// ---------------------------------------------------------------------------
// Elementwise tf32-rounded copy (float4 granularity; n divisible by 1024)
// ---------------------------------------------------------------------------
__global__ void __launch_bounds__(256) round_copy(
    const float* __restrict__ in, float* __restrict__ out)
{
    const long i = ((long)blockIdx.x * 256 + threadIdx.x) * 4;
    float4 v = *(const float4*)(in + i);
    v.x = round_tf32(v.x); v.y = round_tf32(v.y);
    v.z = round_tf32(v.z); v.w = round_tf32(v.w);
    *(float4*)(out + i) = v;
}

// ---------------------------------------------------------------------------
// Softmax over rows of 2048; writes exact weights AND tf32-rounded copy.
// ---------------------------------------------------------------------------
__global__ void __launch_bounds__(256) softmax2048(
    float* __restrict__ data, float* __restrict__ rounded)
{
    __shared__ float red[8];
    float* row  = data    + (long)blockIdx.x * 2048;
    float* rrow = rounded + (long)blockIdx.x * 2048;
    const int tid = threadIdx.x;

    float v[8];
    float m = -3.4e38f;
#pragma unroll
    for (int i = 0; i < 8; ++i) { v[i] = row[tid + 256 * i]; m = fmaxf(m, v[i]); }
#pragma unroll
    for (int s = 16; s > 0; s >>= 1) m = fmaxf(m, __shfl_xor_sync(0xFFFFFFFF, m, s));
    if ((tid & 31) == 0) red[tid >> 5] = m;
    __syncthreads();
    m = red[tid & 7];
#pragma unroll
    for (int s = 4; s > 0; s >>= 1) m = fmaxf(m, __shfl_xor_sync(0xFFFFFFFF, m, s));
    __syncthreads();

    float sum = 0.0f;
#pragma unroll
    for (int i = 0; i < 8; ++i) { v[i] = __expf(v[i] - m); sum += v[i]; }
#pragma unroll
    for (int s = 16; s > 0; s >>= 1) sum += __shfl_xor_sync(0xFFFFFFFF, sum, s);
    if ((tid & 31) == 0) red[tid >> 5] = sum;
    __syncthreads();
    sum = red[tid & 7];
#pragma unroll
    for (int s = 4; s > 0; s >>= 1) sum += __shfl_xor_sync(0xFFFFFFFF, sum, s);

    const float inv = 1.0f / sum;
#pragma unroll
    for (int i = 0; i < 8; ++i) {
        const float w = v[i] * inv;
        row[tid + 256 * i]  = w;
        rrow[tid + 256 * i] = round_tf32(w);
    }
}

// ---------------------------------------------------------------------------
// kernel_launch
// inputs: inputs[B,S,D], Wq[D,U], Wk[D,U], Wv[D,U], Wo[U,D], bo[D], scale
// output: [ output (B*S*D) | weights (B*S*S) ]
// ---------------------------------------------------------------------------
extern "C" void kernel_launch(void* const* d_in, const int* in_sizes, int n_in,
                              void* d_out, int out_size)
{
    const float* x     = (const float*)d_in[0];
    const float* Wq    = (const float*)d_in[1];
    const float* Wk    = (const float*)d_in[2];
    const float* Wv    = (const float*)d_in[3];
    const float* Wo    = (const float*)d_in[4];
    const float* bo    = (const float*)d_in[5];
    const float* scale = (const float*)d_in[6];

    float* out  = (float*)d_out;
    float* wout = (float*)d_out + (long)BB * SS * DD;

    float *qp, *kp, *vt, *ctx, *wr, *wqt, *wkt, *wvt, *wot;
    cudaGetSymbolAddress((void**)&qp,  g_q);
    cudaGetSymbolAddress((void**)&kp,  g_k);
    cudaGetSymbolAddress((void**)&vt,  g_vt);
    cudaGetSymbolAddress((void**)&ctx, g_ctx);
    cudaGetSymbolAddress((void**)&wr,  g_wr);
    cudaGetSymbolAddress((void**)&wqt, g_wqt);
    cudaGetSymbolAddress((void**)&wkt, g_wkt);
    cudaGetSymbolAddress((void**)&wvt, g_wvt);
    cudaGetSymbolAddress((void**)&wot, g_wot);

    float* xr = ctx;   // rounded X aliases g_ctx (dead until GEMM 7 writes it)

    cudaFuncSetAttribute(tf32_gemm<false, false, true>,
                         cudaFuncAttributeMaxDynamicSharedMemorySize, SMEM_TOTAL);
    cudaFuncSetAttribute(tf32_gemm<false, true, false>,
                         cudaFuncAttributeMaxDynamicSharedMemorySize, SMEM_TOTAL);
    cudaFuncSetAttribute(tf32_gemm<true, false, false>,
                         cudaFuncAttributeMaxDynamicSharedMemorySize, SMEM_TOTAL);

    // 0) Round X once (tf32-rounded fp32, raw-stageable)
    round_copy<<<(BB * SS * DD) / 1024, 256>>>(x, xr);

    // 1) Transpose weights with rounding (B operand must be [N, K] rounded)
    {
        dim3 blk(32, 8);
        transpose_k<<<dim3(UU / 32, DD / 32), blk>>>(Wq, wqt, DD, UU);
        transpose_k<<<dim3(UU / 32, DD / 32), blk>>>(Wk, wkt, DD, UU);
        transpose_k<<<dim3(UU / 32, DD / 32), blk>>>(Wv, wvt, DD, UU);
        transpose_k<<<dim3(DD / 32, UU / 32), blk>>>(Wo, wot, UU, DD);
    }

    const int M_all = BB * SS;  // 8192

    // 2) Q = Xr @ Wqt   (rounded output)
    tf32_gemm<false, false, true><<<dim3(UU / 128, M_all / 128, 1), 256, SMEM_TOTAL>>>(
        xr, wqt, qp, DD, DD, DD, UU, 0, 0, 0, nullptr, nullptr);
    // 3) K = Xr @ Wkt   (rounded output)
    tf32_gemm<false, false, true><<<dim3(UU / 128, M_all / 128, 1), 256, SMEM_TOTAL>>>(
        xr, wkt, kp, DD, DD, DD, UU, 0, 0, 0, nullptr, nullptr);
    // 4) Vt[b] = (X_b @ Wv)^T : A=Wvt [U,D], B=Xr_b [S,D]  (rounded output)
    tf32_gemm<false, false, true><<<dim3(SS / 128, UU / 128, BB), 256, SMEM_TOTAL>>>(
        wvt, xr, vt, DD, DD, DD, SS,
        0, (long)SS * DD, (long)UU * SS, nullptr, nullptr);
    // 5) scores[b] = scale * Q_b @ K_b^T  (exact output -> weights)
    tf32_gemm<false, true, false><<<dim3(SS / 128, SS / 128, BB), 256, SMEM_TOTAL>>>(
        qp, kp, wout, UU, UU, UU, SS,
        (long)SS * UU, (long)SS * UU, (long)SS * SS, nullptr, scale);
    // 6) softmax: exact -> wout, rounded -> wr
    softmax2048<<<BB * SS, 256>>>(wout, wr);
    // 7) ctx[b] = weights_b @ V_b : A=wr_b [S,S], B=Vt_b [U,S]  (rounded output)
    tf32_gemm<false, false, true><<<dim3(UU / 128, SS / 128, BB), 256, SMEM_TOTAL>>>(
        wr, vt, ctx, SS, SS, SS, UU,
        (long)SS * SS, (long)UU * SS, (long)SS * UU, nullptr, nullptr);
    // 8) out = ctx @ Wot + bo  (exact output)
    tf32_gemm<true, false, false><<<dim3(DD / 128, M_all / 128, 1), 256, SMEM_TOTAL>>>(
        ctx, wot, out, UU, UU, UU, DD, 0, 0, 0, bo, nullptr);

    (void)in_sizes; (void)n_in; (void)out_size;
}